// round 4
// baseline (speedup 1.0000x reference)
#include <cuda_runtime.h>
#include <cuda_bf16.h>
#include <cstdint>

#define D 64
#define MAXN 50176

// Scratch (static device globals — allocation-free)
__device__ float g_aggX[MAXN * D];   // sum over dst of X[src]
__device__ float g_aggE[MAXN * D];   // sum over dst of edge_in
__device__ float g_deg[MAXN];
__device__ float g_hu2[MAXN * D];    // X @ (W_n2e_u @ W_e2e_bot)
__device__ float g_hv2[MAXN * D];    // [S,X] @ (W_n2e_v @ W_e2e_bot)
__device__ float g_Wcu[D * D];       // composite: W_n2e_u @ W_e2e[64:128]
__device__ float g_Wcv[2 * D * D];   // composite: W_n2e_v @ W_e2e[64:128]

// ---------------------------------------------------------------------------
// K0: zero aggregation scratch (graph replays!)
// ---------------------------------------------------------------------------
__global__ void k_zero(int N) {
    int i = blockIdx.x * blockDim.x + threadIdx.x;
    if (i < N * D) { g_aggX[i] = 0.0f; g_aggE[i] = 0.0f; }
    if (i < N)     g_deg[i] = 0.0f;
}

// ---------------------------------------------------------------------------
// K0b: composite weights Wcu = Wn2e_u @ We2e_bot, Wcv = Wn2e_v @ We2e_bot
// ---------------------------------------------------------------------------
__global__ void k_wcomp(const float* __restrict__ Wn2e_u,
                        const float* __restrict__ Wn2e_v,
                        const float* __restrict__ We2e) {
    int idx = blockIdx.x * blockDim.x + threadIdx.x;
    if (idx < D * D) {
        int r = idx >> 6, j = idx & 63;
        float s = 0.0f;
        #pragma unroll 8
        for (int t = 0; t < D; t++)
            s += __ldg(Wn2e_u + r * D + t) * __ldg(We2e + (D + t) * D + j);
        g_Wcu[idx] = s;
    } else if (idx < D * D + 2 * D * D) {
        int i2 = idx - D * D;
        int r = i2 >> 6, j = i2 & 63;
        float s = 0.0f;
        #pragma unroll 8
        for (int t = 0; t < D; t++)
            s += __ldg(Wn2e_v + r * D + t) * __ldg(We2e + (D + t) * D + j);
        g_Wcv[i2] = s;
    }
}

// ---------------------------------------------------------------------------
// K1: node precompute  hu2 = X@Wcu,  hv2 = S@Wcv[0:64] + X@Wcv[64:128]
// warp per node (4 nodes per warp), weights in shared
// ---------------------------------------------------------------------------
__global__ __launch_bounds__(256) void k_node_pre(const float* __restrict__ S,
                                                  const float* __restrict__ X,
                                                  int N) {
    __shared__ float sWcu[D * D];
    __shared__ float sWcvS[D * D];
    __shared__ float sWcvX[D * D];
    int tid = threadIdx.x;
    for (int i = tid; i < D * D; i += 256) {
        sWcu[i]  = g_Wcu[i];
        sWcvS[i] = g_Wcv[i];
        sWcvX[i] = g_Wcv[D * D + i];
    }
    __syncthreads();

    int warp = tid >> 5, lane = tid & 31;
    #pragma unroll
    for (int it = 0; it < 4; it++) {
        int n = blockIdx.x * 32 + warp * 4 + it;
        if (n >= N) continue;
        size_t base = (size_t)n * D;
        float x0 = X[base + lane], x1 = X[base + lane + 32];
        float s0 = S[base + lane], s1 = S[base + lane + 32];
        float au0 = 0, au1 = 0, av0 = 0, av1 = 0;
        #pragma unroll
        for (int k = 0; k < D; k++) {
            float xk = __shfl_sync(0xffffffffu, (k < 32) ? x0 : x1, k & 31);
            float sk = __shfl_sync(0xffffffffu, (k < 32) ? s0 : s1, k & 31);
            au0 += xk * sWcu[k * D + lane];
            au1 += xk * sWcu[k * D + lane + 32];
            av0 += sk * sWcvS[k * D + lane]      + xk * sWcvX[k * D + lane];
            av1 += sk * sWcvS[k * D + lane + 32] + xk * sWcvX[k * D + lane + 32];
        }
        g_hu2[base + lane] = au0;  g_hu2[base + lane + 32] = au1;
        g_hv2[base + lane] = av0;  g_hv2[base + lane + 32] = av1;
    }
}

// ---------------------------------------------------------------------------
// K_edge: per 64-edge tile:
//   e_out = (edge @ We2e_top) + g_hu2[src] + g_hv2[dst] + bias_e
//   scatter: aggE[dst] += edge, aggX[dst] += X[src], deg[dst] += 1
// Register-tiled 4x4 GEMM, 256 threads (16x16)
// NOTE: g_hu2/g_hv2 referenced DIRECTLY in device code — passing a __device__
// global as a host-side kernel arg passes the host shadow address (silently
// readable via ATS on GB300 → zeros). That was the Round-2 bug.
// ---------------------------------------------------------------------------
__global__ __launch_bounds__(256) void k_edge(const float* __restrict__ edge_in,
                                              const int* __restrict__ src,
                                              const int* __restrict__ dst,
                                              const float* __restrict__ We2e,
                                              const float* __restrict__ bias_e,
                                              const float* __restrict__ X,
                                              float* __restrict__ e_out,
                                              int E) {
    __shared__ float sA[D][65];     // sA[k][e] = edge_in[e][k] (transposed)
    __shared__ float sW[D][D];      // We2e rows 0..63 (top)
    __shared__ int   sSrc[64], sDst[64];

    int tid = threadIdx.x;
    int ebase = blockIdx.x * 64;
    int nE = E - ebase; if (nE > 64) nE = 64;

    for (int i = tid; i < D * D; i += 256)
        sW[i >> 6][i & 63] = We2e[i];

    for (int i = tid; i < 64 * 16; i += 256) {
        int e = i >> 4, q = i & 15;
        float4 v = (e < nE) ? reinterpret_cast<const float4*>(edge_in)[(size_t)(ebase + e) * 16 + q]
                            : make_float4(0.f, 0.f, 0.f, 0.f);
        sA[4 * q + 0][e] = v.x;
        sA[4 * q + 1][e] = v.y;
        sA[4 * q + 2][e] = v.z;
        sA[4 * q + 3][e] = v.w;
    }
    if (tid < 64) {
        sSrc[tid] = (tid < nE) ? src[ebase + tid] : 0;
        sDst[tid] = (tid < nE) ? dst[ebase + tid] : 0;
    }
    __syncthreads();

    int tx = tid & 15, ty = tid >> 4;   // tx: feature group, ty: edge group
    float acc[4][4] = {};
    #pragma unroll 8
    for (int k = 0; k < D; k++) {
        float a0 = sA[k][ty * 4 + 0];
        float a1 = sA[k][ty * 4 + 1];
        float a2 = sA[k][ty * 4 + 2];
        float a3 = sA[k][ty * 4 + 3];
        float4 b = *reinterpret_cast<const float4*>(&sW[k][tx * 4]);
        acc[0][0] += a0 * b.x; acc[0][1] += a0 * b.y; acc[0][2] += a0 * b.z; acc[0][3] += a0 * b.w;
        acc[1][0] += a1 * b.x; acc[1][1] += a1 * b.y; acc[1][2] += a1 * b.z; acc[1][3] += a1 * b.w;
        acc[2][0] += a2 * b.x; acc[2][1] += a2 * b.y; acc[2][2] += a2 * b.z; acc[2][3] += a2 * b.w;
        acc[3][0] += a3 * b.x; acc[3][1] += a3 * b.y; acc[3][2] += a3 * b.z; acc[3][3] += a3 * b.w;
    }

    float4 bb = reinterpret_cast<const float4*>(bias_e)[tx];

    #pragma unroll
    for (int r = 0; r < 4; r++) {
        int e = ty * 4 + r;
        if (e >= nE) continue;
        int s  = sSrc[e];
        int d2 = sDst[e];
        float4 hu = reinterpret_cast<const float4*>(g_hu2)[(size_t)s  * 16 + tx];
        float4 hv = reinterpret_cast<const float4*>(g_hv2)[(size_t)d2 * 16 + tx];
        float4 o;
        o.x = acc[r][0] + hu.x + hv.x + bb.x;
        o.y = acc[r][1] + hu.y + hv.y + bb.y;
        o.z = acc[r][2] + hu.z + hv.z + bb.z;
        o.w = acc[r][3] + hu.w + hv.w + bb.w;
        reinterpret_cast<float4*>(e_out)[(size_t)(ebase + e) * 16 + tx] = o;

        // scatters (compile to RED.F32 — return unused)
        float4 xr = reinterpret_cast<const float4*>(X)[(size_t)s * 16 + tx];
        float* aX = g_aggX + (size_t)d2 * D + tx * 4;
        atomicAdd(aX + 0, xr.x); atomicAdd(aX + 1, xr.y);
        atomicAdd(aX + 2, xr.z); atomicAdd(aX + 3, xr.w);
        float* aE = g_aggE + (size_t)d2 * D + tx * 4;
        atomicAdd(aE + 0, sA[tx * 4 + 0][e]);
        atomicAdd(aE + 1, sA[tx * 4 + 1][e]);
        atomicAdd(aE + 2, sA[tx * 4 + 2][e]);
        atomicAdd(aE + 3, sA[tx * 4 + 3][e]);
        if (tx == 0) atomicAdd(g_deg + d2, 1.0f);
    }
}

// ---------------------------------------------------------------------------
// K2: node output
//   summed = aggX@Wu + aggE@We2n ; hn = summed / max(deg,1)
//   h_out  = [S, X, hn] @ Wv + bias_n
// warp per node (4/warp), two phases sharing one 48KB shared buffer
// ---------------------------------------------------------------------------
__global__ __launch_bounds__(256) void k_node_out(const float* __restrict__ S,
                                                  const float* __restrict__ X,
                                                  const float* __restrict__ Wu,
                                                  const float* __restrict__ We2n,
                                                  const float* __restrict__ Wv,
                                                  const float* __restrict__ bias_n,
                                                  float* __restrict__ h_out,
                                                  int N) {
    __shared__ float sW[3 * D * D];   // 12288 floats = 48KB
    int tid = threadIdx.x;
    int warp = tid >> 5, lane = tid & 31;

    // Phase 1 weights: Wu (0:4096), We2n (4096:8192)
    for (int i = tid; i < 2 * D * D; i += 256)
        sW[i] = (i < D * D) ? Wu[i] : We2n[i - D * D];
    __syncthreads();

    float hn0[4], hn1[4];
    #pragma unroll
    for (int it = 0; it < 4; it++) {
        int n = blockIdx.x * 32 + warp * 4 + it;
        hn0[it] = 0.0f; hn1[it] = 0.0f;
        if (n >= N) continue;
        size_t base = (size_t)n * D;
        float ax0 = g_aggX[base + lane], ax1 = g_aggX[base + lane + 32];
        float ae0 = g_aggE[base + lane], ae1 = g_aggE[base + lane + 32];
        float s0 = 0, s1 = 0;
        #pragma unroll
        for (int k = 0; k < D; k++) {
            float axk = __shfl_sync(0xffffffffu, (k < 32) ? ax0 : ax1, k & 31);
            float aek = __shfl_sync(0xffffffffu, (k < 32) ? ae0 : ae1, k & 31);
            s0 += axk * sW[k * D + lane]      + aek * sW[D * D + k * D + lane];
            s1 += axk * sW[k * D + lane + 32] + aek * sW[D * D + k * D + lane + 32];
        }
        float inv = 1.0f / fmaxf(g_deg[n], 1.0f);
        hn0[it] = s0 * inv;
        hn1[it] = s1 * inv;
    }
    __syncthreads();

    // Phase 2 weights: Wv [192,64]
    for (int i = tid; i < 3 * D * D; i += 256)
        sW[i] = Wv[i];
    __syncthreads();

    float b0 = __ldg(bias_n + lane), b1 = __ldg(bias_n + lane + 32);
    #pragma unroll
    for (int it = 0; it < 4; it++) {
        int n = blockIdx.x * 32 + warp * 4 + it;
        if (n >= N) continue;
        size_t base = (size_t)n * D;
        float sr0 = S[base + lane], sr1 = S[base + lane + 32];
        float xr0 = X[base + lane], xr1 = X[base + lane + 32];
        float a0 = b0, a1 = b1;
        #pragma unroll
        for (int k = 0; k < D; k++) {
            float sk = __shfl_sync(0xffffffffu, (k < 32) ? sr0 : sr1, k & 31);
            float xk = __shfl_sync(0xffffffffu, (k < 32) ? xr0 : xr1, k & 31);
            float hk = (k < 32) ? __shfl_sync(0xffffffffu, hn0[it], k)
                                : __shfl_sync(0xffffffffu, hn1[it], k - 32);
            a0 += sk * sW[k * D + lane]
                + xk * sW[(D + k) * D + lane]
                + hk * sW[(2 * D + k) * D + lane];
            a1 += sk * sW[k * D + lane + 32]
                + xk * sW[(D + k) * D + lane + 32]
                + hk * sW[(2 * D + k) * D + lane + 32];
        }
        h_out[base + lane] = a0;
        h_out[base + lane + 32] = a1;
    }
}

// ---------------------------------------------------------------------------
extern "C" void kernel_launch(void* const* d_in, const int* in_sizes, int n_in,
                              void* d_out, int out_size) {
    const float* S      = (const float*)d_in[0];
    const float* X      = (const float*)d_in[1];
    const float* Ein    = (const float*)d_in[2];
    const int*   src    = (const int*)d_in[3];
    const int*   dst    = (const int*)d_in[4];
    const float* Wn2n_u = (const float*)d_in[5];
    const float* Wn2n_v = (const float*)d_in[6];
    const float* We2n   = (const float*)d_in[7];
    const float* bias_n = (const float*)d_in[8];
    const float* Wn2e_u = (const float*)d_in[9];
    const float* Wn2e_v = (const float*)d_in[10];
    const float* We2e   = (const float*)d_in[11];
    const float* bias_e = (const float*)d_in[12];

    int N = in_sizes[1] / D;
    int E = in_sizes[3];
    float* h_out = (float*)d_out;
    float* e_out = h_out + (size_t)N * D;

    k_zero<<<(N * D + 255) / 256, 256>>>(N);
    k_wcomp<<<(3 * D * D + 255) / 256, 256>>>(Wn2e_u, Wn2e_v, We2e);
    k_node_pre<<<(N + 31) / 32, 256>>>(S, X, N);
    k_edge<<<(E + 63) / 64, 256>>>(Ein, src, dst, We2e, bias_e, X, e_out, E);
    k_node_out<<<(N + 31) / 32, 256>>>(S, X, Wn2n_u, We2n, Wn2n_v, bias_n,
                                       h_out, N);
}

// round 5
// speedup vs baseline: 1.3230x; 1.3230x over previous
#include <cuda_runtime.h>
#include <cuda_bf16.h>
#include <cstdint>

#define D 64
#define MAXN 50176

// Scratch (static device globals — allocation-free). Referenced ONLY in
// device code (host-side symbol is an ATS-readable shadow — Round-2 bug).
__device__ float g_aggX[MAXN * D];   // sum over dst of X[src]
__device__ float g_aggE[MAXN * D];   // sum over dst of edge_in
__device__ float g_deg[MAXN];
__device__ float g_hu2[MAXN * D];    // X @ (W_n2e_u @ W_e2e_bot)
__device__ float g_hv2[MAXN * D];    // [S,X] @ (W_n2e_v @ W_e2e_bot)
__device__ float g_hn[MAXN * D];     // mean-aggregated neighborhood feats
__device__ float g_Wcu[D * D];       // composite: W_n2e_u @ W_e2e[64:128]
__device__ float g_Wcv[2 * D * D];   // composite: W_n2e_v @ W_e2e[64:128]

// ---------------------------------------------------------------------------
// K0: zero aggregation scratch (graph replays!)
// ---------------------------------------------------------------------------
__global__ void k_zero(int N) {
    int i = blockIdx.x * blockDim.x + threadIdx.x;
    int nv = N * D / 4;
    if (i < nv) {
        reinterpret_cast<float4*>(g_aggX)[i] = make_float4(0.f, 0.f, 0.f, 0.f);
        reinterpret_cast<float4*>(g_aggE)[i] = make_float4(0.f, 0.f, 0.f, 0.f);
    }
    if (i < N) g_deg[i] = 0.0f;
}

// ---------------------------------------------------------------------------
// K0b: composite weights Wcu = Wn2e_u @ We2e_bot, Wcv = Wn2e_v @ We2e_bot
// ---------------------------------------------------------------------------
__global__ void k_wcomp(const float* __restrict__ Wn2e_u,
                        const float* __restrict__ Wn2e_v,
                        const float* __restrict__ We2e) {
    int idx = blockIdx.x * blockDim.x + threadIdx.x;
    if (idx < D * D) {
        int r = idx >> 6, j = idx & 63;
        float s = 0.0f;
        #pragma unroll 8
        for (int t = 0; t < D; t++)
            s += __ldg(Wn2e_u + r * D + t) * __ldg(We2e + (D + t) * D + j);
        g_Wcu[idx] = s;
    } else if (idx < D * D + 2 * D * D) {
        int i2 = idx - D * D;
        int r = i2 >> 6, j = i2 & 63;
        float s = 0.0f;
        #pragma unroll 8
        for (int t = 0; t < D; t++)
            s += __ldg(Wn2e_v + r * D + t) * __ldg(We2e + (D + t) * D + j);
        g_Wcv[i2] = s;
    }
}

// ---------------------------------------------------------------------------
// Tile loader helper: load 64 rows x 64 feats, transposed into sT[k][n]
// ---------------------------------------------------------------------------
__device__ __forceinline__ void load_tile_T(float (*sT)[65],
                                            const float* __restrict__ p,
                                            int base, int nRows, int tid) {
    for (int i = tid; i < 64 * 16; i += 256) {
        int n = i >> 4, q = i & 15;
        float4 v = (n < nRows)
            ? reinterpret_cast<const float4*>(p)[(size_t)(base + n) * 16 + q]
            : make_float4(0.f, 0.f, 0.f, 0.f);
        sT[4 * q + 0][n] = v.x;
        sT[4 * q + 1][n] = v.y;
        sT[4 * q + 2][n] = v.z;
        sT[4 * q + 3][n] = v.w;
    }
}

// ---------------------------------------------------------------------------
// K1: node precompute  hu2 = X@Wcu,  hv2 = S@WcvS + X@WcvX
// GEMM-style: 64-node tile, 4x4 register tiling, dynamic smem 82.4KB
// ---------------------------------------------------------------------------
__global__ __launch_bounds__(256) void k_node_pre(const float* __restrict__ S,
                                                  const float* __restrict__ X,
                                                  int N) {
    extern __shared__ float sm[];
    float (*sXT)[65] = (float(*)[65])sm;              // 4160
    float (*sST)[65] = (float(*)[65])(sm + 4160);     // 4160
    float* sWcu  = sm + 8320;                          // 4096
    float* sWcvS = sm + 12416;                         // 4096
    float* sWcvX = sm + 16512;                         // 4096

    int tid = threadIdx.x;
    int base = blockIdx.x * 64;
    int nN = N - base; if (nN > 64) nN = 64;

    for (int i = tid; i < D * D; i += 256) {
        sWcu[i]  = g_Wcu[i];
        sWcvS[i] = g_Wcv[i];
        sWcvX[i] = g_Wcv[D * D + i];
    }
    load_tile_T(sXT, X, base, nN, tid);
    load_tile_T(sST, S, base, nN, tid);
    __syncthreads();

    int tx = tid & 15, ty = tid >> 4;
    float accU[4][4] = {}, accV[4][4] = {};
    #pragma unroll 8
    for (int k = 0; k < D; k++) {
        float x0 = sXT[k][ty * 4 + 0], x1 = sXT[k][ty * 4 + 1];
        float x2 = sXT[k][ty * 4 + 2], x3 = sXT[k][ty * 4 + 3];
        float s0 = sST[k][ty * 4 + 0], s1 = sST[k][ty * 4 + 1];
        float s2 = sST[k][ty * 4 + 2], s3 = sST[k][ty * 4 + 3];
        float4 bu = *reinterpret_cast<const float4*>(&sWcu[k * D + tx * 4]);
        float4 bs = *reinterpret_cast<const float4*>(&sWcvS[k * D + tx * 4]);
        float4 bx = *reinterpret_cast<const float4*>(&sWcvX[k * D + tx * 4]);
        accU[0][0] += x0*bu.x; accU[0][1] += x0*bu.y; accU[0][2] += x0*bu.z; accU[0][3] += x0*bu.w;
        accU[1][0] += x1*bu.x; accU[1][1] += x1*bu.y; accU[1][2] += x1*bu.z; accU[1][3] += x1*bu.w;
        accU[2][0] += x2*bu.x; accU[2][1] += x2*bu.y; accU[2][2] += x2*bu.z; accU[2][3] += x2*bu.w;
        accU[3][0] += x3*bu.x; accU[3][1] += x3*bu.y; accU[3][2] += x3*bu.z; accU[3][3] += x3*bu.w;
        accV[0][0] += s0*bs.x + x0*bx.x; accV[0][1] += s0*bs.y + x0*bx.y;
        accV[0][2] += s0*bs.z + x0*bx.z; accV[0][3] += s0*bs.w + x0*bx.w;
        accV[1][0] += s1*bs.x + x1*bx.x; accV[1][1] += s1*bs.y + x1*bx.y;
        accV[1][2] += s1*bs.z + x1*bx.z; accV[1][3] += s1*bs.w + x1*bx.w;
        accV[2][0] += s2*bs.x + x2*bx.x; accV[2][1] += s2*bs.y + x2*bx.y;
        accV[2][2] += s2*bs.z + x2*bx.z; accV[2][3] += s2*bs.w + x2*bx.w;
        accV[3][0] += s3*bs.x + x3*bx.x; accV[3][1] += s3*bs.y + x3*bx.y;
        accV[3][2] += s3*bs.z + x3*bx.z; accV[3][3] += s3*bs.w + x3*bx.w;
    }

    #pragma unroll
    for (int r = 0; r < 4; r++) {
        int n = ty * 4 + r;
        if (n >= nN) continue;
        size_t o = (size_t)(base + n) * 16 + tx;
        reinterpret_cast<float4*>(g_hu2)[o] =
            make_float4(accU[r][0], accU[r][1], accU[r][2], accU[r][3]);
        reinterpret_cast<float4*>(g_hv2)[o] =
            make_float4(accV[r][0], accV[r][1], accV[r][2], accV[r][3]);
    }
}

// ---------------------------------------------------------------------------
// K_edge: e_out = edge@We2e_top + g_hu2[src] + g_hv2[dst] + bias_e
//         scatter: aggE[dst]+=edge, aggX[dst]+=X[src], deg[dst]+=1
// Scatters use red.global.add.v4.f32 (PTX 8.1, sm_90+): 4x fewer RED wavefronts
// ---------------------------------------------------------------------------
__global__ __launch_bounds__(256) void k_edge(const float* __restrict__ edge_in,
                                              const int* __restrict__ src,
                                              const int* __restrict__ dst,
                                              const float* __restrict__ We2e,
                                              const float* __restrict__ bias_e,
                                              const float* __restrict__ X,
                                              float* __restrict__ e_out,
                                              int E) {
    __shared__ float sA[D][65];     // sA[k][e] = edge_in[e][k] (transposed)
    __shared__ float sW[D][D];      // We2e rows 0..63 (top)
    __shared__ int   sSrc[64], sDst[64];

    int tid = threadIdx.x;
    int ebase = blockIdx.x * 64;
    int nE = E - ebase; if (nE > 64) nE = 64;

    for (int i = tid; i < D * D; i += 256)
        sW[i >> 6][i & 63] = We2e[i];

    for (int i = tid; i < 64 * 16; i += 256) {
        int e = i >> 4, q = i & 15;
        float4 v = (e < nE) ? reinterpret_cast<const float4*>(edge_in)[(size_t)(ebase + e) * 16 + q]
                            : make_float4(0.f, 0.f, 0.f, 0.f);
        sA[4 * q + 0][e] = v.x;
        sA[4 * q + 1][e] = v.y;
        sA[4 * q + 2][e] = v.z;
        sA[4 * q + 3][e] = v.w;
    }
    if (tid < 64) {
        sSrc[tid] = (tid < nE) ? src[ebase + tid] : 0;
        sDst[tid] = (tid < nE) ? dst[ebase + tid] : 0;
    }
    __syncthreads();

    int tx = tid & 15, ty = tid >> 4;
    float acc[4][4] = {};
    #pragma unroll 8
    for (int k = 0; k < D; k++) {
        float a0 = sA[k][ty * 4 + 0];
        float a1 = sA[k][ty * 4 + 1];
        float a2 = sA[k][ty * 4 + 2];
        float a3 = sA[k][ty * 4 + 3];
        float4 b = *reinterpret_cast<const float4*>(&sW[k][tx * 4]);
        acc[0][0] += a0 * b.x; acc[0][1] += a0 * b.y; acc[0][2] += a0 * b.z; acc[0][3] += a0 * b.w;
        acc[1][0] += a1 * b.x; acc[1][1] += a1 * b.y; acc[1][2] += a1 * b.z; acc[1][3] += a1 * b.w;
        acc[2][0] += a2 * b.x; acc[2][1] += a2 * b.y; acc[2][2] += a2 * b.z; acc[2][3] += a2 * b.w;
        acc[3][0] += a3 * b.x; acc[3][1] += a3 * b.y; acc[3][2] += a3 * b.z; acc[3][3] += a3 * b.w;
    }

    float4 bb = reinterpret_cast<const float4*>(bias_e)[tx];

    #pragma unroll
    for (int r = 0; r < 4; r++) {
        int e = ty * 4 + r;
        if (e >= nE) continue;
        int s  = sSrc[e];
        int d2 = sDst[e];
        float4 hu = reinterpret_cast<const float4*>(g_hu2)[(size_t)s  * 16 + tx];
        float4 hv = reinterpret_cast<const float4*>(g_hv2)[(size_t)d2 * 16 + tx];
        float4 o;
        o.x = acc[r][0] + hu.x + hv.x + bb.x;
        o.y = acc[r][1] + hu.y + hv.y + bb.y;
        o.z = acc[r][2] + hu.z + hv.z + bb.z;
        o.w = acc[r][3] + hu.w + hv.w + bb.w;
        reinterpret_cast<float4*>(e_out)[(size_t)(ebase + e) * 16 + tx] = o;

        // vectorized scatters (RED, no return)
        float4 xr = reinterpret_cast<const float4*>(X)[(size_t)s * 16 + tx];
        float* aX = g_aggX + (size_t)d2 * D + tx * 4;
        asm volatile("red.global.add.v4.f32 [%0], {%1,%2,%3,%4};"
                     :: "l"(aX), "f"(xr.x), "f"(xr.y), "f"(xr.z), "f"(xr.w)
                     : "memory");
        float e0 = sA[tx * 4 + 0][e], e1 = sA[tx * 4 + 1][e];
        float e2 = sA[tx * 4 + 2][e], e3 = sA[tx * 4 + 3][e];
        float* aE = g_aggE + (size_t)d2 * D + tx * 4;
        asm volatile("red.global.add.v4.f32 [%0], {%1,%2,%3,%4};"
                     :: "l"(aE), "f"(e0), "f"(e1), "f"(e2), "f"(e3)
                     : "memory");
        if (tx == 0) atomicAdd(g_deg + d2, 1.0f);
    }
}

// ---------------------------------------------------------------------------
// K2a: hn = (aggX@Wu + aggE@We2n) / max(deg,1)
// ---------------------------------------------------------------------------
__global__ __launch_bounds__(256) void k_node_outA(const float* __restrict__ Wu,
                                                   const float* __restrict__ We2n,
                                                   int N) {
    extern __shared__ float sm[];
    float (*sAX)[65] = (float(*)[65])sm;              // 4160
    float (*sAE)[65] = (float(*)[65])(sm + 4160);     // 4160
    float* sWu = sm + 8320;                            // 4096
    float* sWe = sm + 12416;                           // 4096

    int tid = threadIdx.x;
    int base = blockIdx.x * 64;
    int nN = N - base; if (nN > 64) nN = 64;

    for (int i = tid; i < D * D; i += 256) {
        sWu[i] = Wu[i];
        sWe[i] = We2n[i];
    }
    load_tile_T(sAX, g_aggX, base, nN, tid);
    load_tile_T(sAE, g_aggE, base, nN, tid);
    __syncthreads();

    int tx = tid & 15, ty = tid >> 4;
    float acc[4][4] = {};
    #pragma unroll 8
    for (int k = 0; k < D; k++) {
        float a0 = sAX[k][ty * 4 + 0], a1 = sAX[k][ty * 4 + 1];
        float a2 = sAX[k][ty * 4 + 2], a3 = sAX[k][ty * 4 + 3];
        float e0 = sAE[k][ty * 4 + 0], e1 = sAE[k][ty * 4 + 1];
        float e2 = sAE[k][ty * 4 + 2], e3 = sAE[k][ty * 4 + 3];
        float4 bu = *reinterpret_cast<const float4*>(&sWu[k * D + tx * 4]);
        float4 be = *reinterpret_cast<const float4*>(&sWe[k * D + tx * 4]);
        acc[0][0] += a0*bu.x + e0*be.x; acc[0][1] += a0*bu.y + e0*be.y;
        acc[0][2] += a0*bu.z + e0*be.z; acc[0][3] += a0*bu.w + e0*be.w;
        acc[1][0] += a1*bu.x + e1*be.x; acc[1][1] += a1*bu.y + e1*be.y;
        acc[1][2] += a1*bu.z + e1*be.z; acc[1][3] += a1*bu.w + e1*be.w;
        acc[2][0] += a2*bu.x + e2*be.x; acc[2][1] += a2*bu.y + e2*be.y;
        acc[2][2] += a2*bu.z + e2*be.z; acc[2][3] += a2*bu.w + e2*be.w;
        acc[3][0] += a3*bu.x + e3*be.x; acc[3][1] += a3*bu.y + e3*be.y;
        acc[3][2] += a3*bu.z + e3*be.z; acc[3][3] += a3*bu.w + e3*be.w;
    }

    #pragma unroll
    for (int r = 0; r < 4; r++) {
        int n = ty * 4 + r;
        if (n >= nN) continue;
        float inv = 1.0f / fmaxf(g_deg[base + n], 1.0f);
        reinterpret_cast<float4*>(g_hn)[(size_t)(base + n) * 16 + tx] =
            make_float4(acc[r][0] * inv, acc[r][1] * inv,
                        acc[r][2] * inv, acc[r][3] * inv);
    }
}

// ---------------------------------------------------------------------------
// K2b: h_out = S@Wv[0:64] + X@Wv[64:128] + hn@Wv[128:192] + bias_n
// ---------------------------------------------------------------------------
__global__ __launch_bounds__(256) void k_node_outB(const float* __restrict__ S,
                                                   const float* __restrict__ X,
                                                   const float* __restrict__ Wv,
                                                   const float* __restrict__ bias_n,
                                                   float* __restrict__ h_out,
                                                   int N) {
    extern __shared__ float sm[];
    float (*sST)[65] = (float(*)[65])sm;              // 4160
    float (*sXT)[65] = (float(*)[65])(sm + 4160);     // 4160
    float (*sHT)[65] = (float(*)[65])(sm + 8320);     // 4160
    float* sWv = sm + 12480;                           // 12288

    int tid = threadIdx.x;
    int base = blockIdx.x * 64;
    int nN = N - base; if (nN > 64) nN = 64;

    for (int i = tid; i < 3 * D * D; i += 256)
        sWv[i] = Wv[i];
    load_tile_T(sST, S, base, nN, tid);
    load_tile_T(sXT, X, base, nN, tid);
    load_tile_T(sHT, g_hn, base, nN, tid);
    __syncthreads();

    int tx = tid & 15, ty = tid >> 4;
    float4 bb = reinterpret_cast<const float4*>(bias_n)[tx];
    float acc[4][4];
    #pragma unroll
    for (int r = 0; r < 4; r++) {
        acc[r][0] = bb.x; acc[r][1] = bb.y; acc[r][2] = bb.z; acc[r][3] = bb.w;
    }

    #pragma unroll 8
    for (int k = 0; k < D; k++) {
        float4 wS = *reinterpret_cast<const float4*>(&sWv[k * D + tx * 4]);
        float4 wX = *reinterpret_cast<const float4*>(&sWv[(D + k) * D + tx * 4]);
        float4 wH = *reinterpret_cast<const float4*>(&sWv[(2 * D + k) * D + tx * 4]);
        #pragma unroll
        for (int r = 0; r < 4; r++) {
            float s = sST[k][ty * 4 + r];
            float x = sXT[k][ty * 4 + r];
            float h = sHT[k][ty * 4 + r];
            acc[r][0] += s * wS.x + x * wX.x + h * wH.x;
            acc[r][1] += s * wS.y + x * wX.y + h * wH.y;
            acc[r][2] += s * wS.z + x * wX.z + h * wH.z;
            acc[r][3] += s * wS.w + x * wX.w + h * wH.w;
        }
    }

    #pragma unroll
    for (int r = 0; r < 4; r++) {
        int n = ty * 4 + r;
        if (n >= nN) continue;
        reinterpret_cast<float4*>(h_out)[(size_t)(base + n) * 16 + tx] =
            make_float4(acc[r][0], acc[r][1], acc[r][2], acc[r][3]);
    }
}

// ---------------------------------------------------------------------------
extern "C" void kernel_launch(void* const* d_in, const int* in_sizes, int n_in,
                              void* d_out, int out_size) {
    const float* S      = (const float*)d_in[0];
    const float* X      = (const float*)d_in[1];
    const float* Ein    = (const float*)d_in[2];
    const int*   src    = (const int*)d_in[3];
    const int*   dst    = (const int*)d_in[4];
    const float* Wn2n_u = (const float*)d_in[5];
    const float* Wn2n_v = (const float*)d_in[6];
    const float* We2n   = (const float*)d_in[7];
    const float* bias_n = (const float*)d_in[8];
    const float* Wn2e_u = (const float*)d_in[9];
    const float* Wn2e_v = (const float*)d_in[10];
    const float* We2e   = (const float*)d_in[11];
    const float* bias_e = (const float*)d_in[12];

    int N = in_sizes[1] / D;
    int E = in_sizes[3];
    float* h_out = (float*)d_out;
    float* e_out = h_out + (size_t)N * D;

    const int SM_PRE  = 20608 * 4;   // 82432 B
    const int SM_OUTA = 16512 * 4;   // 66048 B
    const int SM_OUTB = 24768 * 4;   // 99072 B
    static bool attr_set = false;
    if (!attr_set) {
        cudaFuncSetAttribute(k_node_pre,  cudaFuncAttributeMaxDynamicSharedMemorySize, SM_PRE);
        cudaFuncSetAttribute(k_node_outA, cudaFuncAttributeMaxDynamicSharedMemorySize, SM_OUTA);
        cudaFuncSetAttribute(k_node_outB, cudaFuncAttributeMaxDynamicSharedMemorySize, SM_OUTB);
        attr_set = true;
    }

    int nBlk = (N + 63) / 64;
    k_zero<<<(N * D / 4 + 255) / 256, 256>>>(N);
    k_wcomp<<<(3 * D * D + 255) / 256, 256>>>(Wn2e_u, Wn2e_v, We2e);
    k_node_pre<<<nBlk, 256, SM_PRE>>>(S, X, N);
    k_edge<<<(E + 63) / 64, 256>>>(Ein, src, dst, We2e, bias_e, X, e_out, E);
    k_node_outA<<<nBlk, 256, SM_OUTA>>>(Wn2n_u, We2n, N);
    k_node_outB<<<nBlk, 256, SM_OUTB>>>(S, X, Wn2n_v, bias_n, h_out, N);
}

// round 6
// speedup vs baseline: 1.5079x; 1.1398x over previous
#include <cuda_runtime.h>
#include <cuda_bf16.h>
#include <cstdint>

#define D 64
#define MAXN 50176

// Scratch (static device globals — allocation-free). Referenced ONLY in
// device code (host-side symbol is an ATS-readable shadow — Round-2 bug).
__device__ float g_aggX[MAXN * D];
__device__ float g_aggE[MAXN * D];
__device__ float g_deg[MAXN];
__device__ float g_hu2[MAXN * D];
__device__ float g_hv2[MAXN * D];
__device__ float g_hn[MAXN * D];
__device__ float g_Wcu[D * D];
__device__ float g_Wcv[2 * D * D];
// B fragments for mma.sync m16n8k8.tf32: [kstep 8][ntile 8][lane 32][2]
__device__ float g_Wmma[8 * 8 * 32 * 2];

// ---------------------------------------------------------------------------
__global__ void k_zero(int N) {
    int i = blockIdx.x * blockDim.x + threadIdx.x;
    int nv = N * D / 4;
    if (i < nv) {
        reinterpret_cast<float4*>(g_aggX)[i] = make_float4(0.f, 0.f, 0.f, 0.f);
        reinterpret_cast<float4*>(g_aggE)[i] = make_float4(0.f, 0.f, 0.f, 0.f);
    }
    if (i < N) g_deg[i] = 0.0f;
}

// ---------------------------------------------------------------------------
// K0b: composite weights Wcu = Wn2e_u @ We2e_bot, Wcv = Wn2e_v @ We2e_bot
// ---------------------------------------------------------------------------
__global__ void k_wcomp(const float* __restrict__ Wn2e_u,
                        const float* __restrict__ Wn2e_v,
                        const float* __restrict__ We2e) {
    int idx = blockIdx.x * blockDim.x + threadIdx.x;
    if (idx < D * D) {
        int r = idx >> 6, j = idx & 63;
        float s = 0.0f;
        #pragma unroll 8
        for (int t = 0; t < D; t++)
            s += __ldg(Wn2e_u + r * D + t) * __ldg(We2e + (D + t) * D + j);
        g_Wcu[idx] = s;
    } else if (idx < D * D + 2 * D * D) {
        int i2 = idx - D * D;
        int r = i2 >> 6, j = i2 & 63;
        float s = 0.0f;
        #pragma unroll 8
        for (int t = 0; t < D; t++)
            s += __ldg(Wn2e_v + r * D + t) * __ldg(We2e + (D + t) * D + j);
        g_Wcv[i2] = s;
    }
}

// ---------------------------------------------------------------------------
// K0c: pre-swizzle We2e top rows into tf32 B-fragment layout.
// b0 = W[ks*8+tig][nt*8+gid], b1 = W[ks*8+tig+4][nt*8+gid]; gid=lane>>2, tig=lane&3
// ---------------------------------------------------------------------------
__global__ void k_wprep(const float* __restrict__ We2e) {
    int i = blockIdx.x * blockDim.x + threadIdx.x;   // 0..2047
    if (i >= 8 * 8 * 32) return;
    int lane = i & 31, nt = (i >> 5) & 7, ks = i >> 8;
    int gid = lane >> 2, tig = lane & 3;
    float w0 = We2e[(ks * 8 + tig) * D + nt * 8 + gid];
    float w1 = We2e[(ks * 8 + tig + 4) * D + nt * 8 + gid];
    uint32_t t0, t1;
    asm("cvt.rna.tf32.f32 %0, %1;" : "=r"(t0) : "f"(w0));
    asm("cvt.rna.tf32.f32 %0, %1;" : "=r"(t1) : "f"(w1));
    g_Wmma[i * 2 + 0] = __uint_as_float(t0);
    g_Wmma[i * 2 + 1] = __uint_as_float(t1);
}

// ---------------------------------------------------------------------------
// Tile loader: 64 rows x 64 feats transposed (node kernels)
// ---------------------------------------------------------------------------
__device__ __forceinline__ void load_tile_T(float (*sT)[65],
                                            const float* __restrict__ p,
                                            int base, int nRows, int tid) {
    for (int i = tid; i < 64 * 16; i += 256) {
        int n = i >> 4, q = i & 15;
        float4 v = (n < nRows)
            ? reinterpret_cast<const float4*>(p)[(size_t)(base + n) * 16 + q]
            : make_float4(0.f, 0.f, 0.f, 0.f);
        sT[4 * q + 0][n] = v.x;
        sT[4 * q + 1][n] = v.y;
        sT[4 * q + 2][n] = v.z;
        sT[4 * q + 3][n] = v.w;
    }
}

// ---------------------------------------------------------------------------
// K1: node precompute  hu2 = X@Wcu,  hv2 = S@WcvS + X@WcvX   (unchanged)
// ---------------------------------------------------------------------------
__global__ __launch_bounds__(256) void k_node_pre(const float* __restrict__ S,
                                                  const float* __restrict__ X,
                                                  int N) {
    extern __shared__ float sm[];
    float (*sXT)[65] = (float(*)[65])sm;
    float (*sST)[65] = (float(*)[65])(sm + 4160);
    float* sWcu  = sm + 8320;
    float* sWcvS = sm + 12416;
    float* sWcvX = sm + 16512;

    int tid = threadIdx.x;
    int base = blockIdx.x * 64;
    int nN = N - base; if (nN > 64) nN = 64;

    for (int i = tid; i < D * D; i += 256) {
        sWcu[i]  = g_Wcu[i];
        sWcvS[i] = g_Wcv[i];
        sWcvX[i] = g_Wcv[D * D + i];
    }
    load_tile_T(sXT, X, base, nN, tid);
    load_tile_T(sST, S, base, nN, tid);
    __syncthreads();

    int tx = tid & 15, ty = tid >> 4;
    float accU[4][4] = {}, accV[4][4] = {};
    #pragma unroll 8
    for (int k = 0; k < D; k++) {
        float x0 = sXT[k][ty * 4 + 0], x1 = sXT[k][ty * 4 + 1];
        float x2 = sXT[k][ty * 4 + 2], x3 = sXT[k][ty * 4 + 3];
        float s0 = sST[k][ty * 4 + 0], s1 = sST[k][ty * 4 + 1];
        float s2 = sST[k][ty * 4 + 2], s3 = sST[k][ty * 4 + 3];
        float4 bu = *reinterpret_cast<const float4*>(&sWcu[k * D + tx * 4]);
        float4 bs = *reinterpret_cast<const float4*>(&sWcvS[k * D + tx * 4]);
        float4 bx = *reinterpret_cast<const float4*>(&sWcvX[k * D + tx * 4]);
        accU[0][0] += x0*bu.x; accU[0][1] += x0*bu.y; accU[0][2] += x0*bu.z; accU[0][3] += x0*bu.w;
        accU[1][0] += x1*bu.x; accU[1][1] += x1*bu.y; accU[1][2] += x1*bu.z; accU[1][3] += x1*bu.w;
        accU[2][0] += x2*bu.x; accU[2][1] += x2*bu.y; accU[2][2] += x2*bu.z; accU[2][3] += x2*bu.w;
        accU[3][0] += x3*bu.x; accU[3][1] += x3*bu.y; accU[3][2] += x3*bu.z; accU[3][3] += x3*bu.w;
        accV[0][0] += s0*bs.x + x0*bx.x; accV[0][1] += s0*bs.y + x0*bx.y;
        accV[0][2] += s0*bs.z + x0*bx.z; accV[0][3] += s0*bs.w + x0*bx.w;
        accV[1][0] += s1*bs.x + x1*bx.x; accV[1][1] += s1*bs.y + x1*bx.y;
        accV[1][2] += s1*bs.z + x1*bx.z; accV[1][3] += s1*bs.w + x1*bx.w;
        accV[2][0] += s2*bs.x + x2*bx.x; accV[2][1] += s2*bs.y + x2*bx.y;
        accV[2][2] += s2*bs.z + x2*bx.z; accV[2][3] += s2*bs.w + x2*bx.w;
        accV[3][0] += s3*bs.x + x3*bx.x; accV[3][1] += s3*bs.y + x3*bx.y;
        accV[3][2] += s3*bs.z + x3*bx.z; accV[3][3] += s3*bs.w + x3*bx.w;
    }

    #pragma unroll
    for (int r = 0; r < 4; r++) {
        int n = ty * 4 + r;
        if (n >= nN) continue;
        size_t o = (size_t)(base + n) * 16 + tx;
        reinterpret_cast<float4*>(g_hu2)[o] =
            make_float4(accU[r][0], accU[r][1], accU[r][2], accU[r][3]);
        reinterpret_cast<float4*>(g_hv2)[o] =
            make_float4(accV[r][0], accV[r][1], accV[r][2], accV[r][3]);
    }
}

// ---------------------------------------------------------------------------
// K_edge v3: tensor-core (tf32 mma.sync) edge GEMM + fused gather/scatter.
// 256 threads, 128 edges/block; warp w owns edges [w*16, w*16+16).
//   e_out = edge@We2e_top (tf32 mma) + g_hu2[src] + g_hv2[dst] + bias_e
//   scatter: aggE[dst]+=edge, aggX[dst]+=X[src], deg[dst]+=1  (fp32 exact)
// Dynamic smem: sE[128][68] fp32 edge-major | sB 4096 | src/dst 128+128
// ---------------------------------------------------------------------------
#define SE_PITCH 68
__global__ __launch_bounds__(256) void k_edge(const float* __restrict__ edge_in,
                                              const int* __restrict__ src,
                                              const int* __restrict__ dst,
                                              const float* __restrict__ bias_e,
                                              const float* __restrict__ X,
                                              float* __restrict__ e_out,
                                              int E) {
    extern __shared__ float sm[];
    float* sE = sm;                        // 128*68 = 8704 floats
    float* sB = sm + 128 * SE_PITCH;       // 4096 floats
    int* sSrc = (int*)(sB + 4096);         // 128
    int* sDst = sSrc + 128;                // 128

    int tid = threadIdx.x;
    int ebase = blockIdx.x * 128;
    int nE = E - ebase; if (nE > 128) nE = 128;

    // load B fragments (conflict-free, identical layout to g_Wmma)
    for (int i = tid; i < 4096; i += 256) sB[i] = g_Wmma[i];

    // load edge tile, edge-major
    #pragma unroll
    for (int it = 0; it < 8; it++) {
        int i = tid + it * 256;            // 0..2047
        int e = i >> 4, q = i & 15;
        float4 v = (e < nE)
            ? reinterpret_cast<const float4*>(edge_in)[(size_t)(ebase + e) * 16 + q]
            : make_float4(0.f, 0.f, 0.f, 0.f);
        *reinterpret_cast<float4*>(&sE[e * SE_PITCH + 4 * q]) = v;
    }
    if (tid < 128) {
        sSrc[tid] = (tid < nE) ? src[ebase + tid] : 0;
        sDst[tid] = (tid < nE) ? dst[ebase + tid] : 0;
    }
    __syncthreads();

    int wid = tid >> 5, lane = tid & 31;
    int gid = lane >> 2, tig = lane & 3;
    int ew = wid * 16;                      // warp's local edge base

    // ---- scatter phase first (REDs drain while mma computes) ----
    #pragma unroll
    for (int it = 0; it < 8; it++) {
        int idx = it * 32 + lane;           // 0..255
        int e = ew + (idx >> 4);            // wait: idx>>4 spans 0..15 only if idx<256
        // idx>>4 = it*2 + (lane>>4)  -> 0..15  ✓
        int q = idx & 15;
        if (ebase + e < E) {
            int s = sSrc[e], d2 = sDst[e];
            float4 ev = *reinterpret_cast<const float4*>(&sE[e * SE_PITCH + 4 * q]);
            float* aE = g_aggE + (size_t)d2 * D + q * 4;
            asm volatile("red.global.add.v4.f32 [%0], {%1,%2,%3,%4};"
                         :: "l"(aE), "f"(ev.x), "f"(ev.y), "f"(ev.z), "f"(ev.w)
                         : "memory");
            float4 xv = reinterpret_cast<const float4*>(X)[(size_t)s * 16 + q];
            float* aX = g_aggX + (size_t)d2 * D + q * 4;
            asm volatile("red.global.add.v4.f32 [%0], {%1,%2,%3,%4};"
                         :: "l"(aX), "f"(xv.x), "f"(xv.y), "f"(xv.z), "f"(xv.w)
                         : "memory");
        }
    }
    if (tid < 128 && tid < nE) atomicAdd(g_deg + sDst[tid], 1.0f);

    // ---- tf32 mma: D[16x64] per warp ----
    float acc[8][4];
    #pragma unroll
    for (int nt = 0; nt < 8; nt++)
        { acc[nt][0] = 0.f; acc[nt][1] = 0.f; acc[nt][2] = 0.f; acc[nt][3] = 0.f; }

    const float* rowA0 = &sE[(ew + gid) * SE_PITCH];
    const float* rowA1 = &sE[(ew + gid + 8) * SE_PITCH];
    #pragma unroll
    for (int ks = 0; ks < 8; ks++) {
        int k0 = ks * 8 + tig;
        uint32_t a0, a1, a2, a3;
        asm("cvt.rna.tf32.f32 %0, %1;" : "=r"(a0) : "f"(rowA0[k0]));
        asm("cvt.rna.tf32.f32 %0, %1;" : "=r"(a1) : "f"(rowA1[k0]));
        asm("cvt.rna.tf32.f32 %0, %1;" : "=r"(a2) : "f"(rowA0[k0 + 4]));
        asm("cvt.rna.tf32.f32 %0, %1;" : "=r"(a3) : "f"(rowA1[k0 + 4]));
        #pragma unroll
        for (int nt = 0; nt < 8; nt++) {
            float2 b = *reinterpret_cast<const float2*>(
                &sB[((ks * 8 + nt) * 32 + lane) * 2]);
            uint32_t b0 = __float_as_uint(b.x), b1 = __float_as_uint(b.y);
            asm volatile(
                "mma.sync.aligned.m16n8k8.row.col.f32.tf32.tf32.f32 "
                "{%0,%1,%2,%3}, {%4,%5,%6,%7}, {%8,%9}, {%0,%1,%2,%3};"
                : "+f"(acc[nt][0]), "+f"(acc[nt][1]),
                  "+f"(acc[nt][2]), "+f"(acc[nt][3])
                : "r"(a0), "r"(a1), "r"(a2), "r"(a3), "r"(b0), "r"(b1));
        }
    }

    // ---- epilogue: add hu2[src] + hv2[dst] + bias, store pairs ----
    int e0 = ew + gid, e1 = ew + gid + 8;
    int s0 = sSrc[e0], d0 = sDst[e0];
    int s1 = sSrc[e1], d1 = sDst[e1];
    bool v0 = (ebase + e0 < E), v1 = (ebase + e1 < E);
    #pragma unroll
    for (int nt = 0; nt < 8; nt++) {
        int n = nt * 8 + 2 * tig;
        float2 bb = *reinterpret_cast<const float2*>(bias_e + n);
        if (v0) {
            float2 hu = *reinterpret_cast<const float2*>(g_hu2 + (size_t)s0 * D + n);
            float2 hv = *reinterpret_cast<const float2*>(g_hv2 + (size_t)d0 * D + n);
            float2 o = make_float2(acc[nt][0] + hu.x + hv.x + bb.x,
                                   acc[nt][1] + hu.y + hv.y + bb.y);
            *reinterpret_cast<float2*>(e_out + (size_t)(ebase + e0) * D + n) = o;
        }
        if (v1) {
            float2 hu = *reinterpret_cast<const float2*>(g_hu2 + (size_t)s1 * D + n);
            float2 hv = *reinterpret_cast<const float2*>(g_hv2 + (size_t)d1 * D + n);
            float2 o = make_float2(acc[nt][2] + hu.x + hv.x + bb.x,
                                   acc[nt][3] + hu.y + hv.y + bb.y);
            *reinterpret_cast<float2*>(e_out + (size_t)(ebase + e1) * D + n) = o;
        }
    }
}

// ---------------------------------------------------------------------------
// K2a: hn = (aggX@Wu + aggE@We2n) / max(deg,1)   (unchanged)
// ---------------------------------------------------------------------------
__global__ __launch_bounds__(256) void k_node_outA(const float* __restrict__ Wu,
                                                   const float* __restrict__ We2n,
                                                   int N) {
    extern __shared__ float sm[];
    float (*sAX)[65] = (float(*)[65])sm;
    float (*sAE)[65] = (float(*)[65])(sm + 4160);
    float* sWu = sm + 8320;
    float* sWe = sm + 12416;

    int tid = threadIdx.x;
    int base = blockIdx.x * 64;
    int nN = N - base; if (nN > 64) nN = 64;

    for (int i = tid; i < D * D; i += 256) {
        sWu[i] = Wu[i];
        sWe[i] = We2n[i];
    }
    load_tile_T(sAX, g_aggX, base, nN, tid);
    load_tile_T(sAE, g_aggE, base, nN, tid);
    __syncthreads();

    int tx = tid & 15, ty = tid >> 4;
    float acc[4][4] = {};
    #pragma unroll 8
    for (int k = 0; k < D; k++) {
        float a0 = sAX[k][ty * 4 + 0], a1 = sAX[k][ty * 4 + 1];
        float a2 = sAX[k][ty * 4 + 2], a3 = sAX[k][ty * 4 + 3];
        float e0 = sAE[k][ty * 4 + 0], e1 = sAE[k][ty * 4 + 1];
        float e2 = sAE[k][ty * 4 + 2], e3 = sAE[k][ty * 4 + 3];
        float4 bu = *reinterpret_cast<const float4*>(&sWu[k * D + tx * 4]);
        float4 be = *reinterpret_cast<const float4*>(&sWe[k * D + tx * 4]);
        acc[0][0] += a0*bu.x + e0*be.x; acc[0][1] += a0*bu.y + e0*be.y;
        acc[0][2] += a0*bu.z + e0*be.z; acc[0][3] += a0*bu.w + e0*be.w;
        acc[1][0] += a1*bu.x + e1*be.x; acc[1][1] += a1*bu.y + e1*be.y;
        acc[1][2] += a1*bu.z + e1*be.z; acc[1][3] += a1*bu.w + e1*be.w;
        acc[2][0] += a2*bu.x + e2*be.x; acc[2][1] += a2*bu.y + e2*be.y;
        acc[2][2] += a2*bu.z + e2*be.z; acc[2][3] += a2*bu.w + e2*be.w;
        acc[3][0] += a3*bu.x + e3*be.x; acc[3][1] += a3*bu.y + e3*be.y;
        acc[3][2] += a3*bu.z + e3*be.z; acc[3][3] += a3*bu.w + e3*be.w;
    }

    #pragma unroll
    for (int r = 0; r < 4; r++) {
        int n = ty * 4 + r;
        if (n >= nN) continue;
        float inv = 1.0f / fmaxf(g_deg[base + n], 1.0f);
        reinterpret_cast<float4*>(g_hn)[(size_t)(base + n) * 16 + tx] =
            make_float4(acc[r][0] * inv, acc[r][1] * inv,
                        acc[r][2] * inv, acc[r][3] * inv);
    }
}

// ---------------------------------------------------------------------------
// K2b: h_out = S@Wv[0:64] + X@Wv[64:128] + hn@Wv[128:192] + bias_n (unchanged)
// ---------------------------------------------------------------------------
__global__ __launch_bounds__(256) void k_node_outB(const float* __restrict__ S,
                                                   const float* __restrict__ X,
                                                   const float* __restrict__ Wv,
                                                   const float* __restrict__ bias_n,
                                                   float* __restrict__ h_out,
                                                   int N) {
    extern __shared__ float sm[];
    float (*sST)[65] = (float(*)[65])sm;
    float (*sXT)[65] = (float(*)[65])(sm + 4160);
    float (*sHT)[65] = (float(*)[65])(sm + 8320);
    float* sWv = sm + 12480;

    int tid = threadIdx.x;
    int base = blockIdx.x * 64;
    int nN = N - base; if (nN > 64) nN = 64;

    for (int i = tid; i < 3 * D * D; i += 256)
        sWv[i] = Wv[i];
    load_tile_T(sST, S, base, nN, tid);
    load_tile_T(sXT, X, base, nN, tid);
    load_tile_T(sHT, g_hn, base, nN, tid);
    __syncthreads();

    int tx = tid & 15, ty = tid >> 4;
    float4 bb = reinterpret_cast<const float4*>(bias_n)[tx];
    float acc[4][4];
    #pragma unroll
    for (int r = 0; r < 4; r++) {
        acc[r][0] = bb.x; acc[r][1] = bb.y; acc[r][2] = bb.z; acc[r][3] = bb.w;
    }

    #pragma unroll 8
    for (int k = 0; k < D; k++) {
        float4 wS = *reinterpret_cast<const float4*>(&sWv[k * D + tx * 4]);
        float4 wX = *reinterpret_cast<const float4*>(&sWv[(D + k) * D + tx * 4]);
        float4 wH = *reinterpret_cast<const float4*>(&sWv[(2 * D + k) * D + tx * 4]);
        #pragma unroll
        for (int r = 0; r < 4; r++) {
            float s = sST[k][ty * 4 + r];
            float x = sXT[k][ty * 4 + r];
            float h = sHT[k][ty * 4 + r];
            acc[r][0] += s * wS.x + x * wX.x + h * wH.x;
            acc[r][1] += s * wS.y + x * wX.y + h * wH.y;
            acc[r][2] += s * wS.z + x * wX.z + h * wH.z;
            acc[r][3] += s * wS.w + x * wX.w + h * wH.w;
        }
    }

    #pragma unroll
    for (int r = 0; r < 4; r++) {
        int n = ty * 4 + r;
        if (n >= nN) continue;
        reinterpret_cast<float4*>(h_out)[(size_t)(base + n) * 16 + tx] =
            make_float4(acc[r][0], acc[r][1], acc[r][2], acc[r][3]);
    }
}

// ---------------------------------------------------------------------------
extern "C" void kernel_launch(void* const* d_in, const int* in_sizes, int n_in,
                              void* d_out, int out_size) {
    const float* S      = (const float*)d_in[0];
    const float* X      = (const float*)d_in[1];
    const float* Ein    = (const float*)d_in[2];
    const int*   src    = (const int*)d_in[3];
    const int*   dst    = (const int*)d_in[4];
    const float* Wn2n_u = (const float*)d_in[5];
    const float* Wn2n_v = (const float*)d_in[6];
    const float* We2n   = (const float*)d_in[7];
    const float* bias_n = (const float*)d_in[8];
    const float* Wn2e_u = (const float*)d_in[9];
    const float* Wn2e_v = (const float*)d_in[10];
    const float* We2e   = (const float*)d_in[11];
    const float* bias_e = (const float*)d_in[12];

    int N = in_sizes[1] / D;
    int E = in_sizes[3];
    float* h_out = (float*)d_out;
    float* e_out = h_out + (size_t)N * D;

    const int SM_PRE  = 20608 * 4;               // 82432 B
    const int SM_OUTA = 16512 * 4;               // 66048 B
    const int SM_OUTB = 24768 * 4;               // 99072 B
    const int SM_EDGE = (128 * SE_PITCH + 4096) * 4 + 256 * 4;  // 52224 B

    cudaFuncSetAttribute(k_node_pre,  cudaFuncAttributeMaxDynamicSharedMemorySize, SM_PRE);
    cudaFuncSetAttribute(k_node_outA, cudaFuncAttributeMaxDynamicSharedMemorySize, SM_OUTA);
    cudaFuncSetAttribute(k_node_outB, cudaFuncAttributeMaxDynamicSharedMemorySize, SM_OUTB);
    cudaFuncSetAttribute(k_edge,      cudaFuncAttributeMaxDynamicSharedMemorySize, SM_EDGE);

    int nBlk = (N + 63) / 64;
    k_zero<<<(N * D / 4 + 255) / 256, 256>>>(N);
    k_wcomp<<<(3 * D * D + 255) / 256, 256>>>(Wn2e_u, Wn2e_v, We2e);
    k_wprep<<<8, 256>>>(We2e);
    k_node_pre<<<nBlk, 256, SM_PRE>>>(S, X, N);
    k_edge<<<(E + 127) / 128, 256, SM_EDGE>>>(Ein, src, dst, bias_e, X, e_out, E);
    k_node_outA<<<nBlk, 256, SM_OUTA>>>(Wn2n_u, We2n, N);
    k_node_outB<<<nBlk, 256, SM_OUTB>>>(S, X, Wn2n_v, bias_n, h_out, N);
}

// round 8
// speedup vs baseline: 1.6079x; 1.0663x over previous
#include <cuda_runtime.h>
#include <cuda_bf16.h>
#include <cstdint>

#define D 64
#define MAXN 50176

// Scratch (static device globals — allocation-free). Referenced ONLY in
// device code (host-side symbol is an ATS-readable shadow — Round-2 bug).
__device__ float g_aggX[MAXN * D];
__device__ float g_aggE[MAXN * D];
__device__ float g_deg[MAXN];
__device__ float g_hu2[MAXN * D];
__device__ float g_hv2[MAXN * D];
__device__ float g_Wcu[D * D];
__device__ float g_Wcv[2 * D * D];
// B fragments for mma.sync m16n8k8.tf32: [kstep 8][ntile 8][lane 32][2]
__device__ float g_Wmma[8 * 8 * 32 * 2];

// ---------------------------------------------------------------------------
__global__ void k_zero(int N) {
    int i = blockIdx.x * blockDim.x + threadIdx.x;
    int nv = N * D / 4;
    if (i < nv) {
        reinterpret_cast<float4*>(g_aggX)[i] = make_float4(0.f, 0.f, 0.f, 0.f);
        reinterpret_cast<float4*>(g_aggE)[i] = make_float4(0.f, 0.f, 0.f, 0.f);
    }
    if (i < N) g_deg[i] = 0.0f;
}

// ---------------------------------------------------------------------------
// K0b: composite weights Wcu = Wn2e_u @ We2e_bot, Wcv = Wn2e_v @ We2e_bot
//      + pre-swizzled tf32 B fragments of We2e_top (merged kernel)
// ---------------------------------------------------------------------------
__global__ void k_wprep(const float* __restrict__ Wn2e_u,
                        const float* __restrict__ Wn2e_v,
                        const float* __restrict__ We2e) {
    int idx = blockIdx.x * blockDim.x + threadIdx.x;
    if (idx < D * D) {
        int r = idx >> 6, j = idx & 63;
        float s = 0.0f;
        #pragma unroll 8
        for (int t = 0; t < D; t++)
            s += __ldg(Wn2e_u + r * D + t) * __ldg(We2e + (D + t) * D + j);
        g_Wcu[idx] = s;
    } else if (idx < 3 * D * D) {
        int i2 = idx - D * D;
        int r = i2 >> 6, j = i2 & 63;
        float s = 0.0f;
        #pragma unroll 8
        for (int t = 0; t < D; t++)
            s += __ldg(Wn2e_v + r * D + t) * __ldg(We2e + (D + t) * D + j);
        g_Wcv[i2] = s;
    } else if (idx < 3 * D * D + 8 * 8 * 32) {
        int i = idx - 3 * D * D;               // 0..2047
        int lane = i & 31, nt = (i >> 5) & 7, ks = i >> 8;
        int gid = lane >> 2, tig = lane & 3;
        float w0 = We2e[(ks * 8 + tig) * D + nt * 8 + gid];
        float w1 = We2e[(ks * 8 + tig + 4) * D + nt * 8 + gid];
        uint32_t t0, t1;
        asm("cvt.rna.tf32.f32 %0, %1;" : "=r"(t0) : "f"(w0));
        asm("cvt.rna.tf32.f32 %0, %1;" : "=r"(t1) : "f"(w1));
        g_Wmma[i * 2 + 0] = __uint_as_float(t0);
        g_Wmma[i * 2 + 1] = __uint_as_float(t1);
    }
}

// ---------------------------------------------------------------------------
// Tile loader: 64 rows x 64 feats transposed (node kernels)
// ---------------------------------------------------------------------------
__device__ __forceinline__ void load_tile_T(float (*sT)[65],
                                            const float* __restrict__ p,
                                            int base, int nRows, int tid) {
    for (int i = tid; i < 64 * 16; i += 256) {
        int n = i >> 4, q = i & 15;
        float4 v = (n < nRows)
            ? reinterpret_cast<const float4*>(p)[(size_t)(base + n) * 16 + q]
            : make_float4(0.f, 0.f, 0.f, 0.f);
        sT[4 * q + 0][n] = v.x;
        sT[4 * q + 1][n] = v.y;
        sT[4 * q + 2][n] = v.z;
        sT[4 * q + 3][n] = v.w;
    }
}

// ---------------------------------------------------------------------------
// K1: node precompute  hu2 = X@Wcu,  hv2 = S@WcvS + X@WcvX
// ---------------------------------------------------------------------------
__global__ __launch_bounds__(256) void k_node_pre(const float* __restrict__ S,
                                                  const float* __restrict__ X,
                                                  int N) {
    extern __shared__ float sm[];
    float (*sXT)[65] = (float(*)[65])sm;
    float (*sST)[65] = (float(*)[65])(sm + 4160);
    float* sWcu  = sm + 8320;
    float* sWcvS = sm + 12416;
    float* sWcvX = sm + 16512;

    int tid = threadIdx.x;
    int base = blockIdx.x * 64;
    int nN = N - base; if (nN > 64) nN = 64;

    for (int i = tid; i < D * D; i += 256) {
        sWcu[i]  = g_Wcu[i];
        sWcvS[i] = g_Wcv[i];
        sWcvX[i] = g_Wcv[D * D + i];
    }
    load_tile_T(sXT, X, base, nN, tid);
    load_tile_T(sST, S, base, nN, tid);
    __syncthreads();

    int tx = tid & 15, ty = tid >> 4;
    float accU[4][4] = {}, accV[4][4] = {};
    #pragma unroll 8
    for (int k = 0; k < D; k++) {
        float x0 = sXT[k][ty * 4 + 0], x1 = sXT[k][ty * 4 + 1];
        float x2 = sXT[k][ty * 4 + 2], x3 = sXT[k][ty * 4 + 3];
        float s0 = sST[k][ty * 4 + 0], s1 = sST[k][ty * 4 + 1];
        float s2 = sST[k][ty * 4 + 2], s3 = sST[k][ty * 4 + 3];
        float4 bu = *reinterpret_cast<const float4*>(&sWcu[k * D + tx * 4]);
        float4 bs = *reinterpret_cast<const float4*>(&sWcvS[k * D + tx * 4]);
        float4 bx = *reinterpret_cast<const float4*>(&sWcvX[k * D + tx * 4]);
        accU[0][0] += x0*bu.x; accU[0][1] += x0*bu.y; accU[0][2] += x0*bu.z; accU[0][3] += x0*bu.w;
        accU[1][0] += x1*bu.x; accU[1][1] += x1*bu.y; accU[1][2] += x1*bu.z; accU[1][3] += x1*bu.w;
        accU[2][0] += x2*bu.x; accU[2][1] += x2*bu.y; accU[2][2] += x2*bu.z; accU[2][3] += x2*bu.w;
        accU[3][0] += x3*bu.x; accU[3][1] += x3*bu.y; accU[3][2] += x3*bu.z; accU[3][3] += x3*bu.w;
        accV[0][0] += s0*bs.x + x0*bx.x; accV[0][1] += s0*bs.y + x0*bx.y;
        accV[0][2] += s0*bs.z + x0*bx.z; accV[0][3] += s0*bs.w + x0*bx.w;
        accV[1][0] += s1*bs.x + x1*bx.x; accV[1][1] += s1*bs.y + x1*bx.y;
        accV[1][2] += s1*bs.z + x1*bx.z; accV[1][3] += s1*bs.w + x1*bx.w;
        accV[2][0] += s2*bs.x + x2*bx.x; accV[2][1] += s2*bs.y + x2*bx.y;
        accV[2][2] += s2*bs.z + x2*bx.z; accV[2][3] += s2*bs.w + x2*bx.w;
        accV[3][0] += s3*bs.x + x3*bx.x; accV[3][1] += s3*bs.y + x3*bx.y;
        accV[3][2] += s3*bs.z + x3*bx.z; accV[3][3] += s3*bs.w + x3*bx.w;
    }

    #pragma unroll
    for (int r = 0; r < 4; r++) {
        int n = ty * 4 + r;
        if (n >= nN) continue;
        size_t o = (size_t)(base + n) * 16 + tx;
        reinterpret_cast<float4*>(g_hu2)[o] =
            make_float4(accU[r][0], accU[r][1], accU[r][2], accU[r][3]);
        reinterpret_cast<float4*>(g_hv2)[o] =
            make_float4(accV[r][0], accV[r][1], accV[r][2], accV[r][3]);
    }
}

// ---------------------------------------------------------------------------
// K_edge v4: tf32 mma edge GEMM + fused gather/scatter.
//   - scatter phase (REDs, fire-and-forget) overlapped before mma
//   - epilogue gathers hu2[src]+hv2[dst] into smem (float4, row-coalesced),
//     reusing the sE buffer, then adds per-fragment from smem
// ---------------------------------------------------------------------------
#define SE_PITCH 68
__global__ __launch_bounds__(256, 3)
void k_edge(const float* __restrict__ edge_in,
            const int* __restrict__ src,
            const int* __restrict__ dst,
            const float* __restrict__ bias_e,
            const float* __restrict__ X,
            float* __restrict__ e_out,
            int E) {
    extern __shared__ float sm[];
    float* sE = sm;                        // 128*68 = 8704 floats
    float* sB = sm + 128 * SE_PITCH;       // 4096 floats
    int* sSrc = (int*)(sB + 4096);         // 128
    int* sDst = sSrc + 128;                // 128

    int tid = threadIdx.x;
    int ebase = blockIdx.x * 128;
    int nE = E - ebase; if (nE > 128) nE = 128;

    for (int i = tid; i < 4096; i += 256) sB[i] = g_Wmma[i];

    #pragma unroll
    for (int it = 0; it < 8; it++) {
        int i = tid + it * 256;
        int e = i >> 4, q = i & 15;
        float4 v = (e < nE)
            ? reinterpret_cast<const float4*>(edge_in)[(size_t)(ebase + e) * 16 + q]
            : make_float4(0.f, 0.f, 0.f, 0.f);
        *reinterpret_cast<float4*>(&sE[e * SE_PITCH + 4 * q]) = v;
    }
    if (tid < 128) {
        sSrc[tid] = (tid < nE) ? src[ebase + tid] : 0;
        sDst[tid] = (tid < nE) ? dst[ebase + tid] : 0;
    }
    __syncthreads();

    int wid = tid >> 5, lane = tid & 31;
    int gid = lane >> 2, tig = lane & 3;
    int ew = wid * 16;

    // ---- scatter phase (REDs drain while mma computes) ----
    #pragma unroll
    for (int it = 0; it < 8; it++) {
        int idx = it * 32 + lane;
        int e = ew + (idx >> 4);           // 0..15 within warp's 16 edges
        int q = idx & 15;
        if (ebase + e < E) {
            int s = sSrc[e], d2 = sDst[e];
            float4 ev = *reinterpret_cast<const float4*>(&sE[e * SE_PITCH + 4 * q]);
            float* aE = g_aggE + (size_t)d2 * D + q * 4;
            asm volatile("red.global.add.v4.f32 [%0], {%1,%2,%3,%4};"
                         :: "l"(aE), "f"(ev.x), "f"(ev.y), "f"(ev.z), "f"(ev.w)
                         : "memory");
            float4 xv = reinterpret_cast<const float4*>(X)[(size_t)s * 16 + q];
            float* aX = g_aggX + (size_t)d2 * D + q * 4;
            asm volatile("red.global.add.v4.f32 [%0], {%1,%2,%3,%4};"
                         :: "l"(aX), "f"(xv.x), "f"(xv.y), "f"(xv.z), "f"(xv.w)
                         : "memory");
        }
    }
    if (tid < 128 && tid < nE) atomicAdd(g_deg + sDst[tid], 1.0f);

    // ---- tf32 mma: D[16x64] per warp ----
    float acc[8][4];
    #pragma unroll
    for (int nt = 0; nt < 8; nt++)
        { acc[nt][0] = 0.f; acc[nt][1] = 0.f; acc[nt][2] = 0.f; acc[nt][3] = 0.f; }

    const float* rowA0 = &sE[(ew + gid) * SE_PITCH];
    const float* rowA1 = &sE[(ew + gid + 8) * SE_PITCH];
    #pragma unroll
    for (int ks = 0; ks < 8; ks++) {
        int k0 = ks * 8 + tig;
        uint32_t a0, a1, a2, a3;
        asm("cvt.rna.tf32.f32 %0, %1;" : "=r"(a0) : "f"(rowA0[k0]));
        asm("cvt.rna.tf32.f32 %0, %1;" : "=r"(a1) : "f"(rowA1[k0]));
        asm("cvt.rna.tf32.f32 %0, %1;" : "=r"(a2) : "f"(rowA0[k0 + 4]));
        asm("cvt.rna.tf32.f32 %0, %1;" : "=r"(a3) : "f"(rowA1[k0 + 4]));
        #pragma unroll
        for (int nt = 0; nt < 8; nt++) {
            float2 b = *reinterpret_cast<const float2*>(
                &sB[((ks * 8 + nt) * 32 + lane) * 2]);
            uint32_t b0 = __float_as_uint(b.x), b1 = __float_as_uint(b.y);
            asm volatile(
                "mma.sync.aligned.m16n8k8.row.col.f32.tf32.tf32.f32 "
                "{%0,%1,%2,%3}, {%4,%5,%6,%7}, {%8,%9}, {%0,%1,%2,%3};"
                : "+f"(acc[nt][0]), "+f"(acc[nt][1]),
                  "+f"(acc[nt][2]), "+f"(acc[nt][3])
                : "r"(a0), "r"(a1), "r"(a2), "r"(a3), "r"(b0), "r"(b1));
        }
    }
    __syncthreads();   // all sE reads done

    // ---- gather hu2[src]+hv2[dst] into sE (row-coalesced float4) ----
    #pragma unroll
    for (int it = 0; it < 8; it++) {
        int i = tid + it * 256;
        int e = i >> 4, q = i & 15;
        int s = sSrc[e], d2 = sDst[e];
        float4 hu = reinterpret_cast<const float4*>(g_hu2)[(size_t)s  * 16 + q];
        float4 hv = reinterpret_cast<const float4*>(g_hv2)[(size_t)d2 * 16 + q];
        *reinterpret_cast<float4*>(&sE[e * SE_PITCH + 4 * q]) =
            make_float4(hu.x + hv.x, hu.y + hv.y, hu.z + hv.z, hu.w + hv.w);
    }
    __syncthreads();

    // ---- epilogue: acc + (hu+hv) + bias ----
    int e0 = ew + gid, e1 = ew + gid + 8;
    bool v0 = (ebase + e0 < E), v1 = (ebase + e1 < E);
    #pragma unroll
    for (int nt = 0; nt < 8; nt++) {
        int n = nt * 8 + 2 * tig;
        float2 bb = *reinterpret_cast<const float2*>(bias_e + n);
        if (v0) {
            float2 g = *reinterpret_cast<const float2*>(&sE[e0 * SE_PITCH + n]);
            *reinterpret_cast<float2*>(e_out + (size_t)(ebase + e0) * D + n) =
                make_float2(acc[nt][0] + g.x + bb.x, acc[nt][1] + g.y + bb.y);
        }
        if (v1) {
            float2 g = *reinterpret_cast<const float2*>(&sE[e1 * SE_PITCH + n]);
            *reinterpret_cast<float2*>(e_out + (size_t)(ebase + e1) * D + n) =
                make_float2(acc[nt][2] + g.x + bb.x, acc[nt][3] + g.y + bb.y);
        }
    }
}

// ---------------------------------------------------------------------------
// K2 fused: phase1 hn = (aggX@Wu + aggE@We2n)/max(deg,1)  (regs)
//           phase2 h_out = S@Wv0 + X@Wv1 + hn@Wv2 + bias_n
// hn never touches global memory.
// ---------------------------------------------------------------------------
__global__ __launch_bounds__(256) void k_node_out(const float* __restrict__ S,
                                                  const float* __restrict__ X,
                                                  const float* __restrict__ Wu,
                                                  const float* __restrict__ We2n,
                                                  const float* __restrict__ Wv,
                                                  const float* __restrict__ bias_n,
                                                  float* __restrict__ h_out,
                                                  int N) {
    extern __shared__ float sm[];
    int tid = threadIdx.x;
    int base = blockIdx.x * 64;
    int nN = N - base; if (nN > 64) nN = 64;
    int tx = tid & 15, ty = tid >> 4;

    // ---- phase 1 ----
    {
        float (*sAX)[65] = (float(*)[65])sm;            // 0..4160
        float (*sAE)[65] = (float(*)[65])(sm + 4160);   // ..8320
        float* sWu = sm + 8320;                          // ..12416
        float* sWe = sm + 12416;                         // ..16512
        for (int i = tid; i < D * D; i += 256) {
            sWu[i] = Wu[i];
            sWe[i] = We2n[i];
        }
        load_tile_T(sAX, g_aggX, base, nN, tid);
        load_tile_T(sAE, g_aggE, base, nN, tid);
        __syncthreads();

        float acc[4][4] = {};
        #pragma unroll 8
        for (int k = 0; k < D; k++) {
            float a0 = sAX[k][ty * 4 + 0], a1 = sAX[k][ty * 4 + 1];
            float a2 = sAX[k][ty * 4 + 2], a3 = sAX[k][ty * 4 + 3];
            float e0 = sAE[k][ty * 4 + 0], e1 = sAE[k][ty * 4 + 1];
            float e2 = sAE[k][ty * 4 + 2], e3 = sAE[k][ty * 4 + 3];
            float4 bu = *reinterpret_cast<const float4*>(&sWu[k * D + tx * 4]);
            float4 be = *reinterpret_cast<const float4*>(&sWe[k * D + tx * 4]);
            acc[0][0] += a0*bu.x + e0*be.x; acc[0][1] += a0*bu.y + e0*be.y;
            acc[0][2] += a0*bu.z + e0*be.z; acc[0][3] += a0*bu.w + e0*be.w;
            acc[1][0] += a1*bu.x + e1*be.x; acc[1][1] += a1*bu.y + e1*be.y;
            acc[1][2] += a1*bu.z + e1*be.z; acc[1][3] += a1*bu.w + e1*be.w;
            acc[2][0] += a2*bu.x + e2*be.x; acc[2][1] += a2*bu.y + e2*be.y;
            acc[2][2] += a2*bu.z + e2*be.z; acc[2][3] += a2*bu.w + e2*be.w;
            acc[3][0] += a3*bu.x + e3*be.x; acc[3][1] += a3*bu.y + e3*be.y;
            acc[3][2] += a3*bu.z + e3*be.z; acc[3][3] += a3*bu.w + e3*be.w;
        }
        __syncthreads();   // phase-1 smem reads done

        // write hn (deg-scaled) transposed into sm+8320 (overwrites Wu/We)
        float (*sHT)[65] = (float(*)[65])(sm + 8320);   // ..12480
        #pragma unroll
        for (int r = 0; r < 4; r++) {
            float inv = 1.0f / fmaxf(g_deg[base + ty * 4 + r], 1.0f);
            #pragma unroll
            for (int c = 0; c < 4; c++)
                sHT[tx * 4 + c][ty * 4 + r] = acc[r][c] * inv;
        }
    }

    // ---- phase 2 ----
    float (*sST)[65] = (float(*)[65])sm;                // 0..4160
    float (*sXT)[65] = (float(*)[65])(sm + 4160);       // ..8320
    float (*sHT)[65] = (float(*)[65])(sm + 8320);       // ..12480
    float* sWv = sm + 12480;                             // ..24768
    for (int i = tid; i < 3 * D * D; i += 256)
        sWv[i] = Wv[i];
    load_tile_T(sST, S, base, nN, tid);
    load_tile_T(sXT, X, base, nN, tid);
    __syncthreads();

    float4 bb = reinterpret_cast<const float4*>(bias_n)[tx];
    float acc[4][4];
    #pragma unroll
    for (int r = 0; r < 4; r++) {
        acc[r][0] = bb.x; acc[r][1] = bb.y; acc[r][2] = bb.z; acc[r][3] = bb.w;
    }

    #pragma unroll 8
    for (int k = 0; k < D; k++) {
        float4 wS = *reinterpret_cast<const float4*>(&sWv[k * D + tx * 4]);
        float4 wX = *reinterpret_cast<const float4*>(&sWv[(D + k) * D + tx * 4]);
        float4 wH = *reinterpret_cast<const float4*>(&sWv[(2 * D + k) * D + tx * 4]);
        #pragma unroll
        for (int r = 0; r < 4; r++) {
            float s = sST[k][ty * 4 + r];
            float x = sXT[k][ty * 4 + r];
            float h = sHT[k][ty * 4 + r];
            acc[r][0] += s * wS.x + x * wX.x + h * wH.x;
            acc[r][1] += s * wS.y + x * wX.y + h * wH.y;
            acc[r][2] += s * wS.z + x * wX.z + h * wH.z;
            acc[r][3] += s * wS.w + x * wX.w + h * wH.w;
        }
    }

    #pragma unroll
    for (int r = 0; r < 4; r++) {
        int n = ty * 4 + r;
        if (n >= nN) continue;
        reinterpret_cast<float4*>(h_out)[(size_t)(base + n) * 16 + tx] =
            make_float4(acc[r][0], acc[r][1], acc[r][2], acc[r][3]);
    }
}

// ---------------------------------------------------------------------------
extern "C" void kernel_launch(void* const* d_in, const int* in_sizes, int n_in,
                              void* d_out, int out_size) {
    const float* S      = (const float*)d_in[0];
    const float* X      = (const float*)d_in[1];
    const float* Ein    = (const float*)d_in[2];
    const int*   src    = (const int*)d_in[3];
    const int*   dst    = (const int*)d_in[4];
    const float* Wn2n_u = (const float*)d_in[5];
    const float* Wn2n_v = (const float*)d_in[6];
    const float* We2n   = (const float*)d_in[7];
    const float* bias_n = (const float*)d_in[8];
    const float* Wn2e_u = (const float*)d_in[9];
    const float* Wn2e_v = (const float*)d_in[10];
    const float* We2e   = (const float*)d_in[11];
    const float* bias_e = (const float*)d_in[12];

    int N = in_sizes[1] / D;
    int E = in_sizes[3];
    float* h_out = (float*)d_out;
    float* e_out = h_out + (size_t)N * D;

    const int SM_PRE  = 20608 * 4;                               // 82432 B
    const int SM_OUT  = 24768 * 4;                               // 99072 B
    const int SM_EDGE = (128 * SE_PITCH + 4096) * 4 + 256 * 4;   // 52224 B

    cudaFuncSetAttribute(k_node_pre, cudaFuncAttributeMaxDynamicSharedMemorySize, SM_PRE);
    cudaFuncSetAttribute(k_node_out, cudaFuncAttributeMaxDynamicSharedMemorySize, SM_OUT);
    cudaFuncSetAttribute(k_edge,     cudaFuncAttributeMaxDynamicSharedMemorySize, SM_EDGE);

    int nBlk = (N + 63) / 64;
    k_zero<<<(N * D / 4 + 255) / 256, 256>>>(N);
    k_wprep<<<(3 * D * D + 8 * 8 * 32 + 255) / 256, 256>>>(Wn2e_u, Wn2e_v, We2e);
    k_node_pre<<<nBlk, 256, SM_PRE>>>(S, X, N);
    k_edge<<<(E + 127) / 128, 256, SM_EDGE>>>(Ein, src, dst, bias_e, X, e_out, E);
    k_node_out<<<nBlk, 256, SM_OUT>>>(S, X, Wn2n_u, We2n, Wn2n_v, bias_n, h_out, N);
}